// round 5
// baseline (speedup 1.0000x reference)
#include <cuda_runtime.h>
#include <math.h>

#define NNODES 100000
#define NEDGES 1600000

// ---------------- scratch (static device globals; no allocations) ----------------
__device__ float g_agg [(size_t)NNODES * 192];   // per-rel aggregated sums
__device__ float g_gi  [(size_t)NNODES * 192];   // gi
__device__ float g_gh  [(size_t)NNODES * 192];   // gh (layer 1)
__device__ float g_out [(size_t)NNODES * 64];    // embed lin (raw, pre-BN)
__device__ float g_h   [(size_t)NNODES * 64];    // GRU hidden
__device__ float g_swh [(size_t)NNODES * 64];    // aggregated+transformed messages
__device__ float g_tmp [(size_t)NNODES * 64];    // head hidden
__device__ float g_stats[512];                   // 4 slots x (sum[64], sumsq[64])
__device__ float g_scale[4 * 64];
__device__ float g_shift[4 * 64];
__device__ int   g_rowptr[NNODES + 1];
__device__ int   g_cursor[NNODES];
__device__ int   g_ekey [NEDGES];                // (src<<2)|rel, CSR order
__device__ float g_enorm[NEDGES];                // norm, CSR order
__device__ int   g_bsums[128];

// ---------------- f32x2 helpers ----------------
typedef unsigned long long u64t;

__device__ __forceinline__ u64t pk2(float x) {
    u64t r; asm("mov.b64 %0, {%1, %1};" : "=l"(r) : "f"(x)); return r;
}
__device__ __forceinline__ void fma2(u64t& c, u64t a, u64t b) {
    asm("fma.rn.f32x2 %0, %1, %2, %0;" : "+l"(c) : "l"(a), "l"(b));
}
__device__ __forceinline__ void upk2(u64t v, float& lo, float& hi) {
    asm("mov.b64 {%0, %1}, %2;" : "=f"(lo), "=f"(hi) : "l"(v));
}
__device__ __forceinline__ float sigm(float x) { return 1.0f / (1.0f + expf(-x)); }

// ---------------- CSR build ----------------
__global__ void k_count(const int* __restrict__ dst, int* __restrict__ cnt) {
    int e = blockIdx.x * blockDim.x + threadIdx.x;
    if (e < NEDGES) atomicAdd(&cnt[dst[e]], 1);
}

__global__ void k_scanA(const int* __restrict__ cnt, int* __restrict__ bsums) {
    __shared__ int sh[1024];
    int i = blockIdx.x * 1024 + threadIdx.x;
    sh[threadIdx.x] = (i < NNODES) ? cnt[i] : 0;
    __syncthreads();
    for (int off = 512; off > 0; off >>= 1) {
        if (threadIdx.x < off) sh[threadIdx.x] += sh[threadIdx.x + off];
        __syncthreads();
    }
    if (threadIdx.x == 0) bsums[blockIdx.x] = sh[0];
}

__global__ void k_scanB(int* __restrict__ bsums, int nb, int* __restrict__ rowptr) {
    __shared__ int sh[128];
    int t = threadIdx.x;
    int orig = (t < nb) ? bsums[t] : 0;
    sh[t] = orig;
    __syncthreads();
    for (int off = 1; off < 128; off <<= 1) {
        int v = (t >= off) ? sh[t - off] : 0;
        __syncthreads();
        sh[t] += v;
        __syncthreads();
    }
    if (t < nb) bsums[t] = sh[t] - orig;   // exclusive
    if (t == 0) rowptr[NNODES] = NEDGES;
}

__global__ void k_scanC(int* __restrict__ cnt, const int* __restrict__ bsums,
                        int* __restrict__ rowptr, int* __restrict__ cursor) {
    __shared__ int sh[1024];
    int i = blockIdx.x * 1024 + threadIdx.x;
    int orig = (i < NNODES) ? cnt[i] : 0;
    sh[threadIdx.x] = orig;
    __syncthreads();
    for (int off = 1; off < 1024; off <<= 1) {
        int v = (threadIdx.x >= off) ? sh[threadIdx.x - off] : 0;
        __syncthreads();
        sh[threadIdx.x] += v;
        __syncthreads();
    }
    if (i < NNODES) {
        int start = bsums[blockIdx.x] + sh[threadIdx.x] - orig;
        rowptr[i] = start;
        cursor[i] = start;
    }
}

__global__ void k_scatter(const int* __restrict__ dst, const int* __restrict__ src,
                          const int* __restrict__ rel, const float* __restrict__ norm,
                          int* __restrict__ cursor,
                          int* __restrict__ ekey, float* __restrict__ enorm) {
    int e = blockIdx.x * blockDim.x + threadIdx.x;
    if (e < NEDGES) {
        int pos = atomicAdd(&cursor[dst[e]], 1);
        ekey[pos]  = (src[e] << 2) | rel[e];
        enorm[pos] = norm[e];
    }
}

// ---------------- FFMA2 matmul: 128 nodes x 64 out-cols, KB input blocks ----------
// C[n, blockIdx.y*64 + k] = sum_{kb} act(A[n, kb*64 + :64]) dot Wblk(kb)_col(k)  (+bias)
// Wblk(kb) base = W + blockIdx.y*w_y_stride + kb*w_k_stride
//   transW ? Wb[k*64+d] : Wb[d*64+k]
// in_act: 0 none, 1 affine (only valid for KB==1)
// stats: optional (grid.y==1 only) per-col sum & sumsq of outputs
template <int KB>
__global__ __launch_bounds__(128) void k_mm(
    const float* __restrict__ A, int a_stride,
    const float* __restrict__ W, int transW, int w_y_stride, int w_k_stride,
    const float* __restrict__ bias, int bias_blk,
    const float* __restrict__ in_scale, const float* __restrict__ in_shift, int in_act,
    float* __restrict__ C, int c_stride,
    float* __restrict__ stats)
{
    __shared__ float Ws[64 * 64];     // 16 KB
    __shared__ float As[128 * 64];    // 32 KB (static total 48 KB)
    int tx = threadIdx.x, ty = threadIdx.y;
    int tid = ty * 8 + tx;
    int nbase = blockIdx.x * 128;

    u64t acc[8][4];
#pragma unroll
    for (int j = 0; j < 8; j++)
#pragma unroll
        for (int q = 0; q < 4; q++) acc[j][q] = 0ull;

#pragma unroll
    for (int kb = 0; kb < KB; kb++) {
        if (kb > 0) __syncthreads();          // previous iteration fully consumed
        const float* Wb = W + (size_t)blockIdx.y * w_y_stride + (size_t)kb * w_k_stride;
        for (int i = tid; i < 4096; i += 128) {
            int d = i >> 6, k = i & 63;
            Ws[i] = transW ? Wb[k * 64 + d] : Wb[i];
        }
        for (int i = tid; i < 2048; i += 128) {
            int n = nbase + (i >> 4);
            int c4 = (i & 15);
            float4 v = make_float4(0.f, 0.f, 0.f, 0.f);
            if (n < NNODES)
                v = reinterpret_cast<const float4*>(A + (size_t)n * a_stride + kb * 64)[c4];
            if (in_act) {
                int c = c4 * 4;
                v.x = v.x * in_scale[c]     + in_shift[c];
                v.y = v.y * in_scale[c + 1] + in_shift[c + 1];
                v.z = v.z * in_scale[c + 2] + in_shift[c + 2];
                v.w = v.w * in_scale[c + 3] + in_shift[c + 3];
            }
            reinterpret_cast<float4*>(As)[i] = v;
        }
        __syncthreads();

#pragma unroll 4
        for (int d = 0; d < 64; d++) {
            const u64t* wp = reinterpret_cast<const u64t*>(Ws + d * 64) + tx * 4;
            u64t w0 = wp[0], w1 = wp[1], w2 = wp[2], w3 = wp[3];
            const float* ap = As + ty * 64 + d;
#pragma unroll
            for (int j = 0; j < 8; j++) {
                u64t aa = pk2(ap[j * 16 * 64]);
                fma2(acc[j][0], aa, w0);
                fma2(acc[j][1], aa, w1);
                fma2(acc[j][2], aa, w2);
                fma2(acc[j][3], aa, w3);
            }
        }
    }

    float bv[8];
#pragma unroll
    for (int c = 0; c < 8; c++) bv[c] = 0.f;
    if (bias) {
        const float* bb = bias + blockIdx.y * bias_blk + tx * 8;
#pragma unroll
        for (int c = 0; c < 8; c++) bv[c] = bb[c];
    }

    float s[8], q[8];
#pragma unroll
    for (int c = 0; c < 8; c++) { s[c] = 0.f; q[c] = 0.f; }

#pragma unroll
    for (int j = 0; j < 8; j++) {
        int node = nbase + ty + 16 * j;
        if (node < NNODES) {
            float o[8];
#pragma unroll
            for (int qq = 0; qq < 4; qq++) upk2(acc[j][qq], o[qq * 2], o[qq * 2 + 1]);
#pragma unroll
            for (int c = 0; c < 8; c++) {
                o[c] += bv[c];
                s[c] += o[c];
                q[c] += o[c] * o[c];
            }
            float* cp = C + (size_t)node * c_stride + blockIdx.y * 64 + tx * 8;
            reinterpret_cast<float4*>(cp)[0] = make_float4(o[0], o[1], o[2], o[3]);
            reinterpret_cast<float4*>(cp)[1] = make_float4(o[4], o[5], o[6], o[7]);
        }
    }

    if (stats) {
        __syncthreads();
        float* ssum = Ws;
        float* ssq  = Ws + 64;
        if (tid < 64) { ssum[tid] = 0.f; ssq[tid] = 0.f; }
        __syncthreads();
#pragma unroll
        for (int c = 0; c < 8; c++) {
            atomicAdd(&ssum[tx * 8 + c], s[c]);
            atomicAdd(&ssq [tx * 8 + c], q[c]);
        }
        __syncthreads();
        if (tid < 64) {
            atomicAdd(&stats[tid], ssum[tid]);
            atomicAdd(&stats[64 + tid], ssq[tid]);
        }
    }
}

// ---------------- BN helpers ----------------
__global__ void k_finalize(const float* __restrict__ stats, const float* __restrict__ gamma,
                           const float* __restrict__ beta, float* __restrict__ scale,
                           float* __restrict__ shift) {
    int k = threadIdx.x;
    const float invN = 1.0f / (float)NNODES;
    float mean = stats[k] * invN;
    float var = stats[64 + k] * invN - mean * mean;
    float sc = gamma[k] * rsqrtf(var + 1e-5f);
    scale[k] = sc;
    shift[k] = beta[k] - mean * sc;
}

__global__ void k_stats64(const float* __restrict__ X, float* __restrict__ stats) {
    __shared__ float ssum[64], ssq[64];
    int k = threadIdx.x, ty = threadIdx.y;
    if (ty == 0) { ssum[k] = 0.f; ssq[k] = 0.f; }
    __syncthreads();
    float s = 0.f, q = 0.f;
    for (int n = blockIdx.x * 4 + ty; n < NNODES; n += gridDim.x * 4) {
        float v = X[(size_t)n * 64 + k];
        s += v; q += v * v;
    }
    atomicAdd(&ssum[k], s); atomicAdd(&ssq[k], q);
    __syncthreads();
    if (ty == 0) { atomicAdd(&stats[k], ssum[k]); atomicAdd(&stats[64 + k], ssq[k]); }
}

// ---------------- rel-split edge aggregation (warp per node) ----------------
// agg[v, r*64 + d] = sum over CSR edges of node v with rel r of norm * act(in[src, d])
template <int AFF>
__global__ void k_aggregate(const float* __restrict__ in, const int* __restrict__ rowptr,
                            const int* __restrict__ ekey, const float* __restrict__ enorm,
                            const float* __restrict__ scale, const float* __restrict__ shift,
                            float* __restrict__ agg) {
    int node = (blockIdx.x * blockDim.x + threadIdx.x) >> 5;
    int lane = threadIdx.x & 31;
    if (node >= NNODES) return;
    float sc0 = 1.f, sc1 = 1.f, sf0 = 0.f, sf1 = 0.f;
    if (AFF) { sc0 = scale[lane]; sc1 = scale[lane + 32];
               sf0 = shift[lane]; sf1 = shift[lane + 32]; }
    int beg = rowptr[node], end = rowptr[node + 1];
    float a00 = 0.f, a01 = 0.f, a10 = 0.f, a11 = 0.f, a20 = 0.f, a21 = 0.f;
    for (int e = beg; e < end; ++e) {
        int k0 = ekey[e];
        float w = enorm[e];
        const float* row = in + (size_t)(k0 >> 2) * 64;
        float v0 = row[lane], v1 = row[lane + 32];
        if (AFF) {
            v0 = fmaxf(v0 * sc0 + sf0, 0.f);
            v1 = fmaxf(v1 * sc1 + sf1, 0.f);
        }
        int r = k0 & 3;
        if (r == 0)      { a00 = fmaf(v0, w, a00); a01 = fmaf(v1, w, a01); }
        else if (r == 1) { a10 = fmaf(v0, w, a10); a11 = fmaf(v1, w, a11); }
        else             { a20 = fmaf(v0, w, a20); a21 = fmaf(v1, w, a21); }
    }
    float* o = agg + (size_t)node * 192;
    o[lane] = a00;       o[lane + 32] = a01;
    o[64 + lane] = a10;  o[96 + lane] = a11;
    o[128 + lane] = a20; o[160 + lane] = a21;
}

// ---------------- GRU gate fusion (R2-proven) ----------------
// layer 0: h == 0, so gh == bhh exactly
__global__ void k_gates0(const float* __restrict__ gi, const float* __restrict__ bhh,
                         float* __restrict__ h) {
    size_t idx = (size_t)blockIdx.x * blockDim.x + threadIdx.x;
    if (idx >= (size_t)NNODES * 64) return;
    int n = (int)(idx >> 6), k = (int)(idx & 63);
    size_t b = (size_t)n * 192;
    float r = sigm(gi[b + k] + bhh[k]);
    float z = sigm(gi[b + 64 + k] + bhh[64 + k]);
    float nn = tanhf(gi[b + 128 + k] + r * bhh[128 + k]);
    h[idx] = (1.0f - z) * nn;
}

__global__ void k_gates(const float* __restrict__ gi, const float* __restrict__ gh,
                        float* __restrict__ h) {
    size_t idx = (size_t)blockIdx.x * blockDim.x + threadIdx.x;
    if (idx >= (size_t)NNODES * 64) return;
    int n = (int)(idx >> 6), k = (int)(idx & 63);
    size_t b = (size_t)n * 192;
    float r = sigm(gi[b + k] + gh[b + k]);
    float z = sigm(gi[b + 64 + k] + gh[b + 64 + k]);
    float nn = tanhf(gi[b + 128 + k] + r * gh[b + 128 + k]);
    float hv = h[idx];
    h[idx] = (1.0f - z) * nn + z * hv;
}

// ---------------- head output: relu(BN(tmp)) @ W2.T + b2 ----------------
template <int KO>
__global__ void k_head(const float* __restrict__ X, const float* __restrict__ scale,
                       const float* __restrict__ shift, const float* __restrict__ W2,
                       const float* __restrict__ b2, float* __restrict__ out) {
    __shared__ float Wsh[KO * 65];
    __shared__ float sc[64], sf[64];
    int tid = threadIdx.x;
    for (int i = tid; i < KO * 64; i += 256) {
        int k = i >> 6, d = i & 63;
        Wsh[k * 65 + d] = W2[i];
    }
    if (tid < 64) { sc[tid] = scale[tid]; sf[tid] = shift[tid]; }
    __syncthreads();
    int warp = tid >> 5, lane = tid & 31;
    int n = blockIdx.x * 8 + warp;
    if (n >= NNODES) return;
    float acc = (lane < KO) ? b2[lane] : 0.f;
    const float* row = X + (size_t)n * 64;
    for (int d = 0; d < 64; d++) {
        float x = fmaxf(row[d] * sc[d] + sf[d], 0.f);
        if (lane < KO) acc = fmaf(x, Wsh[lane * 65 + d], acc);
    }
    if (lane < KO) out[(size_t)n * KO + lane] = acc;
}

// ---------------- launch ----------------
extern "C" void kernel_launch(void* const* d_in, const int* in_sizes, int n_in,
                              void* d_out, int out_size) {
    const float* v      = (const float*)d_in[0];
    const int*   src    = (const int*)d_in[1];
    const int*   dst    = (const int*)d_in[2];
    const int*   rel    = (const int*)d_in[3];
    const float* norm   = (const float*)d_in[4];
    const float* emb_W  = (const float*)d_in[5];
    const float* emb_b  = (const float*)d_in[6];
    const float* emb_g  = (const float*)d_in[7];
    const float* emb_be = (const float*)d_in[8];
    const float* relW   = (const float*)d_in[9];
    const float* Wih    = (const float*)d_in[10];
    const float* Whh    = (const float*)d_in[11];
    const float* bih    = (const float*)d_in[12];
    const float* bhh    = (const float*)d_in[13];
    const float* ker_g  = (const float*)d_in[14];
    const float* ker_be = (const float*)d_in[15];
    const float* aW1 = (const float*)d_in[16];
    const float* ab1 = (const float*)d_in[17];
    const float* ag  = (const float*)d_in[18];
    const float* abe = (const float*)d_in[19];
    const float* aW2 = (const float*)d_in[20];
    const float* ab2 = (const float*)d_in[21];
    const float* bW1 = (const float*)d_in[22];
    const float* bb1 = (const float*)d_in[23];
    const float* bg  = (const float*)d_in[24];
    const float* bbe = (const float*)d_in[25];
    const float* bW2 = (const float*)d_in[26];
    const float* bb2 = (const float*)d_in[27];
    float* out = (float*)d_out;

    float *p_agg, *p_gi, *p_gh, *p_out, *p_h, *p_swh, *p_tmp, *p_stats, *p_scale, *p_shift;
    int *p_rowptr, *p_cursor, *p_ekey, *p_bsums;
    float *p_enorm;
    cudaGetSymbolAddress((void**)&p_agg,  g_agg);
    cudaGetSymbolAddress((void**)&p_gi,   g_gi);
    cudaGetSymbolAddress((void**)&p_gh,   g_gh);
    cudaGetSymbolAddress((void**)&p_out,  g_out);
    cudaGetSymbolAddress((void**)&p_h,    g_h);
    cudaGetSymbolAddress((void**)&p_swh,  g_swh);
    cudaGetSymbolAddress((void**)&p_tmp,  g_tmp);
    cudaGetSymbolAddress((void**)&p_stats, g_stats);
    cudaGetSymbolAddress((void**)&p_scale, g_scale);
    cudaGetSymbolAddress((void**)&p_shift, g_shift);
    cudaGetSymbolAddress((void**)&p_rowptr, g_rowptr);
    cudaGetSymbolAddress((void**)&p_cursor, g_cursor);
    cudaGetSymbolAddress((void**)&p_ekey,  g_ekey);
    cudaGetSymbolAddress((void**)&p_enorm, g_enorm);
    cudaGetSymbolAddress((void**)&p_bsums, g_bsums);

    dim3 mmblk(8, 16);
    int mmgx = (NNODES + 127) / 128;               // 782
    const int NSCAN = (NNODES + 1023) / 1024;      // 98
    int aggrid = (NNODES * 32 + 255) / 256;

    // launch #5 (counting the two memsets) is the embedding k_mm<1> for ncu
    cudaMemsetAsync(p_cursor, 0, NNODES * sizeof(int));                       // 0
    cudaMemsetAsync(p_stats, 0, 512 * sizeof(float));                         // 1
    k_count<<<(NEDGES + 255) / 256, 256>>>(dst, p_cursor);                    // 2
    k_scanA<<<NSCAN, 1024>>>(p_cursor, p_bsums);                              // 3
    k_scanB<<<1, 128>>>(p_bsums, NSCAN, p_rowptr);                            // 4
    k_mm<1><<<dim3(mmgx, 1), mmblk>>>(v, 64, emb_W, 1, 0, 0, emb_b, 0,        // 5 PROFILED
                                      nullptr, nullptr, 0, p_out, 64, p_stats);
    k_finalize<<<1, 64>>>(p_stats, emb_g, emb_be, p_scale, p_shift);          // 6
    k_scanC<<<NSCAN, 1024>>>(p_cursor, p_bsums, p_rowptr, p_cursor);          // 7
    k_scatter<<<(NEDGES + 255) / 256, 256>>>(dst, src, rel, norm, p_cursor,   // 8
                                             p_ekey, p_enorm);

    // ---- layer 0: aggregate(relu(bn(emb))) per-rel -> 192->64 mm -> gi mm -> gates ----
    k_aggregate<1><<<aggrid, 256>>>(p_out, p_rowptr, p_ekey, p_enorm,
                                    p_scale, p_shift, p_agg);
    k_mm<3><<<dim3(mmgx, 1), mmblk>>>(p_agg, 192, relW, 0, 0, 4096, nullptr, 0,
                                      nullptr, nullptr, 0, p_swh, 64, nullptr);
    k_mm<1><<<dim3(mmgx, 3), mmblk>>>(p_swh, 64, Wih, 1, 4096, 0, bih, 64,
                                      nullptr, nullptr, 0, p_gi, 192, nullptr);
    k_gates0<<<25000, 256>>>(p_gi, bhh, p_h);

    // ---- layer 1 ----
    k_aggregate<0><<<aggrid, 256>>>(p_h, p_rowptr, p_ekey, p_enorm,
                                    nullptr, nullptr, p_agg);
    k_mm<3><<<dim3(mmgx, 1), mmblk>>>(p_agg, 192, relW, 0, 0, 4096, nullptr, 0,
                                      nullptr, nullptr, 0, p_swh, 64, nullptr);
    k_mm<1><<<dim3(mmgx, 3), mmblk>>>(p_swh, 64, Wih, 1, 4096, 0, bih, 64,
                                      nullptr, nullptr, 0, p_gi, 192, nullptr);
    k_mm<1><<<dim3(mmgx, 3), mmblk>>>(p_h, 64, Whh, 1, 4096, 0, bhh, 64,
                                      nullptr, nullptr, 0, p_gh, 192, nullptr);
    k_gates<<<25000, 256>>>(p_gi, p_gh, p_h);

    // ---- kernel BN on h ----
    k_stats64<<<256, dim3(64, 4)>>>(p_h, p_stats + 128);
    k_finalize<<<1, 64>>>(p_stats + 128, ker_g, ker_be, p_scale + 64, p_shift + 64);

    // ---- head A ----
    k_mm<1><<<dim3(mmgx, 1), mmblk>>>(p_h, 64, aW1, 1, 0, 0, ab1, 0,
                                      p_scale + 64, p_shift + 64, 1, p_tmp, 64,
                                      p_stats + 256);
    k_finalize<<<1, 64>>>(p_stats + 256, ag, abe, p_scale + 128, p_shift + 128);
    k_head<2><<<12500, 256>>>(p_tmp, p_scale + 128, p_shift + 128, aW2, ab2, out);

    // ---- head B ----
    k_mm<1><<<dim3(mmgx, 1), mmblk>>>(p_h, 64, bW1, 1, 0, 0, bb1, 0,
                                      p_scale + 64, p_shift + 64, 1, p_tmp, 64,
                                      p_stats + 384);
    k_finalize<<<1, 64>>>(p_stats + 384, bg, bbe, p_scale + 192, p_shift + 192);
    k_head<21><<<12500, 256>>>(p_tmp, p_scale + 192, p_shift + 192, bW2, bb2,
                               out + (size_t)NNODES * 2);
}